// round 1
// baseline (speedup 1.0000x reference)
#include <cuda_runtime.h>

// PatchesCreate: [64, 384, 384, 3] f32 -> [64, 576, 768] f32
// Each patch row = 16 px * 3 ch = 48 floats = 192 B, contiguous in BOTH
// input and output. So the op is a permutation of 192B chunks = 12 float4s.
//
// Output float4 layout: [B=64][patch=576][e=192]  (e = py*12 + lane)
// Input  float4 layout: [B=64][y=384][row=288]    (row = gx*12 + lane)
// Mapping: patch = gy*24 + gx ; y = gy*16 + py.

static constexpr int B = 64;
static constexpr int OUT4_PER_B = 576 * 192;       // float4 per batch in output
static constexpr int TOTAL4 = B * OUT4_PER_B;      // 7,077,888

__global__ void __launch_bounds__(256)
patches_kernel(const float4* __restrict__ in, float4* __restrict__ out)
{
    int i = blockIdx.x * 256 + threadIdx.x;
    if (i >= TOTAL4) return;

    int e     = i % 192;          // float4 within patch
    int t     = i / 192;
    int patch = t % 576;
    int b     = t / 576;

    int gy   = patch / 24;
    int gx   = patch - gy * 24;
    int py   = e / 12;
    int lane = e - py * 12;

    int y   = gy * 16 + py;
    int in4 = (b * 384 + y) * 288 + gx * 12 + lane;

    out[i] = in[in4];
}

extern "C" void kernel_launch(void* const* d_in, const int* in_sizes, int n_in,
                              void* d_out, int out_size)
{
    (void)in_sizes; (void)n_in; (void)out_size;
    const float4* in  = (const float4*)d_in[0];
    float4*       out = (float4*)d_out;

    int blocks = (TOTAL4 + 255) / 256;   // 27,648
    patches_kernel<<<blocks, 256>>>(in, out);
}

// round 2
// speedup vs baseline: 1.0078x; 1.0078x over previous
#include <cuda_runtime.h>

// PatchesCreate: [64, 384, 384, 3] f32 -> [64, 576, 768] f32
// Permutation of 192B chunks (patch row = 16px * 3ch = 48 floats), moved as
// float4s. Unroll x4 per thread for MLP: 4 independent LDG.128 front-batched,
// then 4 STG.128. Streaming cache hints (.cs) since every byte is single-use.

static constexpr int TOTAL4 = 64 * 576 * 192;   // 7,077,888 float4s
static constexpr int TPB    = 256;
static constexpr int UNROLL = 4;
static constexpr int TILE   = TPB * UNROLL;     // 1024 float4 per block
static constexpr int BLOCKS = TOTAL4 / TILE;    // 6912 exactly

__device__ __forceinline__ int in_index4(int i)
{
    int e     = i % 192;          // float4 within patch
    int t     = i / 192;
    int patch = t % 576;
    int b     = t / 576;

    int gy   = patch / 24;
    int gx   = patch - gy * 24;
    int py   = e / 12;
    int lane = e - py * 12;

    int y = gy * 16 + py;
    return (b * 384 + y) * 288 + gx * 12 + lane;
}

__global__ void __launch_bounds__(TPB)
patches_kernel(const float4* __restrict__ in, float4* __restrict__ out)
{
    int base = blockIdx.x * TILE + threadIdx.x;

    int idx[UNROLL];
    float4 v[UNROLL];

#pragma unroll
    for (int u = 0; u < UNROLL; ++u)
        idx[u] = in_index4(base + u * TPB);

#pragma unroll
    for (int u = 0; u < UNROLL; ++u)
        v[u] = __ldcs(&in[idx[u]]);

#pragma unroll
    for (int u = 0; u < UNROLL; ++u)
        __stcs(&out[base + u * TPB], v[u]);
}

extern "C" void kernel_launch(void* const* d_in, const int* in_sizes, int n_in,
                              void* d_out, int out_size)
{
    (void)in_sizes; (void)n_in; (void)out_size;
    const float4* in  = (const float4*)d_in[0];
    float4*       out = (float4*)d_out;

    patches_kernel<<<BLOCKS, TPB>>>(in, out);
}

// round 3
// speedup vs baseline: 1.0591x; 1.0509x over previous
#include <cuda_runtime.h>

// PatchesCreate: [64, 384, 384, 3] f32 -> [64, 576, 768] f32
// Permutation of 192B chunks (patch row = 16px * 3ch = 48 floats), moved as
// float4s. Unroll x8 per thread: 8 independent LDG.E.128 front-batched
// (MLP_p1=8), then 8 STG.E.128. Streaming hints: every byte single-use.

static constexpr int TOTAL4 = 64 * 576 * 192;   // 7,077,888 float4s
static constexpr int TPB    = 256;
static constexpr int UNROLL = 8;
static constexpr int TILE   = TPB * UNROLL;     // 2048 float4 per block
static constexpr int BLOCKS = TOTAL4 / TILE;    // 3456 exactly, no tail

__device__ __forceinline__ int in_index4(int i)
{
    int e     = i % 192;          // float4 within patch
    int t     = i / 192;
    int patch = t % 576;
    int b     = t / 576;

    int gy   = patch / 24;
    int gx   = patch - gy * 24;
    int py   = e / 12;
    int lane = e - py * 12;

    int y = gy * 16 + py;
    return (b * 384 + y) * 288 + gx * 12 + lane;
}

__global__ void __launch_bounds__(TPB)
patches_kernel(const float4* __restrict__ in, float4* __restrict__ out)
{
    int base = blockIdx.x * TILE + threadIdx.x;

    int idx[UNROLL];
#pragma unroll
    for (int u = 0; u < UNROLL; ++u)
        idx[u] = in_index4(base + u * TPB);

    float4 v[UNROLL];
#pragma unroll
    for (int u = 0; u < UNROLL; ++u)
        v[u] = __ldcs(&in[idx[u]]);

#pragma unroll
    for (int u = 0; u < UNROLL; ++u)
        __stcs(&out[base + u * TPB], v[u]);
}

extern "C" void kernel_launch(void* const* d_in, const int* in_sizes, int n_in,
                              void* d_out, int out_size)
{
    (void)in_sizes; (void)n_in; (void)out_size;
    const float4* in  = (const float4*)d_in[0];
    float4*       out = (float4*)d_out;

    patches_kernel<<<BLOCKS, TPB>>>(in, out);
}